// round 13
// baseline (speedup 1.0000x reference)
#include <cuda_runtime.h>
#include <cuda_fp16.h>
#include <math.h>
#include <stdint.h>

// Problem shape (fixed by setup_inputs)
#define BATCH 4
#define CDIM  512
#define NPTS  8192
#define KNN   16
#define NCHUNK 4
#define KNN_CH (NPTS / NCHUNK)   // 2048 candidates per chunk CTA

// ===========================================================================
// helpers
// ===========================================================================
__device__ __forceinline__ uint32_t smem_to_u32(const void* p) {
    uint32_t a;
    asm("{ .reg .u64 t; cvta.to.shared.u64 t, %1; cvt.u32.u64 %0, t; }" : "=r"(a) : "l"(p));
    return a;
}
__device__ __forceinline__ uint32_t f22h(float a, float b) {
    __half2 h = __floats2half2_rn(a, b);
    return *reinterpret_cast<uint32_t*>(&h);
}
__device__ __forceinline__ void ldsm_x4(uint32_t& r0, uint32_t& r1, uint32_t& r2,
                                        uint32_t& r3, uint32_t addr) {
    asm volatile("ldmatrix.sync.aligned.m8n8.x4.shared.b16 {%0,%1,%2,%3}, [%4];"
                 : "=r"(r0), "=r"(r1), "=r"(r2), "=r"(r3) : "r"(addr));
}
__device__ __forceinline__ void ldsm_x2t(uint32_t& r0, uint32_t& r1, uint32_t addr) {
    asm volatile("ldmatrix.sync.aligned.m8n8.x2.trans.shared.b16 {%0,%1}, [%2];"
                 : "=r"(r0), "=r"(r1) : "r"(addr));
}
__device__ __forceinline__ void mma_f16(float* d, uint32_t a0, uint32_t a1,
                                        uint32_t a2, uint32_t a3,
                                        uint32_t b0, uint32_t b1) {
    asm volatile(
        "mma.sync.aligned.m16n8k16.row.col.f32.f16.f16.f32 "
        "{%0,%1,%2,%3}, {%4,%5,%6,%7}, {%8,%9}, {%0,%1,%2,%3};"
        : "+f"(d[0]), "+f"(d[1]), "+f"(d[2]), "+f"(d[3])
        : "r"(a0), "r"(a1), "r"(a2), "r"(a3), "r"(b0), "r"(b1));
}

// Partial top-16 scratch: [b][n][chunk][16]
__device__ float pd_buf[(size_t)BATCH * NPTS * NCHUNK * KNN];
__device__ int   pi_buf[(size_t)BATCH * NPTS * NCHUNK * KNN];

// ===========================================================================
// KNN partial kernel: grid (queryBlock=32, chunk=4, batch=4) = 512 CTAs.
// Each CTA scans ONE 2048-candidate chunk for its 256 queries and emits a
// sorted (desc) partial top-16 per query.
// Arithmetic replicates the reference's fp32 roundings exactly:
//   xx  = ((x*x) + (y*y)) + (z*z)
//   dot = fma(z,z', fma(y,y', x*x'))
//   d   = fma(2, dot, -xx_n) - xx_m
// Scan m ascending + strict '>' => lower index first on ties (lax.top_k).
// ===========================================================================
__global__ __launch_bounds__(256, 3)
void knn_partial_kernel(const float* __restrict__ xyz)
{
    __shared__ float4 sh[KNN_CH];
    const int b     = blockIdx.z;
    const int chunk = blockIdx.y;
    const float* xb = xyz + (size_t)b * 3 * NPTS;

    const int base = chunk * KNN_CH;
    for (int m = threadIdx.x; m < KNN_CH; m += blockDim.x) {
        float x = xb[base + m];
        float y = xb[NPTS + base + m];
        float z = xb[2 * NPTS + base + m];
        float xx = __fadd_rn(__fadd_rn(__fmul_rn(x, x), __fmul_rn(y, y)),
                             __fmul_rn(z, z));
        sh[m] = make_float4(x, y, z, xx);
    }

    const int n = blockIdx.x * blockDim.x + threadIdx.x;
    float qx = xb[n], qy = xb[NPTS + n], qz = xb[2 * NPTS + n];
    const float nqxx = -__fadd_rn(__fadd_rn(__fmul_rn(qx, qx), __fmul_rn(qy, qy)),
                                  __fmul_rn(qz, qz));

    float dk[KNN];
    int   ik[KNN];
#pragma unroll
    for (int j = 0; j < KNN; ++j) { dk[j] = -3.402823466e38f; ik[j] = 0; }

    __syncthreads();

#pragma unroll 4
    for (int mm = 0; mm < KNN_CH; ++mm) {
        float4 cd = sh[mm];
        float dot = __fmaf_rn(qz, cd.z, __fmaf_rn(qy, cd.y, __fmul_rn(qx, cd.x)));
        float d = __fsub_rn(__fmaf_rn(2.0f, dot, nqxx), cd.w);
        if (d > dk[KNN - 1]) {
            dk[KNN - 1] = d;
            ik[KNN - 1] = base + mm;
#pragma unroll
            for (int j = KNN - 1; j > 0; --j) {
                if (dk[j] > dk[j - 1]) {
                    float td = dk[j]; dk[j] = dk[j - 1]; dk[j - 1] = td;
                    int   ti = ik[j]; ik[j] = ik[j - 1]; ik[j - 1] = ti;
                }
            }
        }
    }

    const size_t o = (((size_t)b * NPTS + n) * NCHUNK + chunk) * KNN;
#pragma unroll
    for (int j = 0; j < KNN; ++j) { pd_buf[o + j] = dk[j]; pi_buf[o + j] = ik[j]; }
}

// ===========================================================================
// Merge kernel: 4-way merge of sorted partial lists per query.
// Strict '>' with chunk index ascending => on ties the lower chunk (= lower
// global index) wins; within-chunk order already index-ascending on ties.
// Exactly reproduces the single-scan global top-16 ordering.
// ===========================================================================
__global__ __launch_bounds__(256)
void knn_merge_kernel(float* __restrict__ out_idx)
{
    const int g = blockIdx.x * blockDim.x + threadIdx.x;   // b*NPTS + n
    const float* pd = pd_buf + (size_t)g * NCHUNK * KNN;
    const int*   pi = pi_buf + (size_t)g * NCHUNK * KNN;
    float* o = out_idx + (size_t)g * KNN;

    int p[NCHUNK] = {0, 0, 0, 0};
#pragma unroll
    for (int j = 0; j < KNN; ++j) {
        float best = -3.402823466e38f;
        int bc = 0;
#pragma unroll
        for (int c = 0; c < NCHUNK; ++c) {
            if (p[c] < KNN) {
                float v = pd[c * KNN + p[c]];
                if (v > best) { best = v; bc = c; }
            }
        }
        o[j] = (float)pi[bc * KNN + p[bc]];
        p[bc]++;
    }
}

// ===========================================================================
// Dual fp16 mma.sync GEMM + BN + ReLU + add. (unchanged from R10 pass)
// ===========================================================================
#define KT 32
#define WPITCH 40
#define FPITCH 136
#define NKT (CDIM / KT)

__global__ __launch_bounds__(256, 1)
void gemm_mma_kernel(const float* __restrict__ feat,
                     const float* __restrict__ wl,
                     const float* __restrict__ wg,
                     const float* __restrict__ gamma_l, const float* __restrict__ beta_l,
                     const float* __restrict__ mean_l,  const float* __restrict__ var_l,
                     const float* __restrict__ gamma_g, const float* __restrict__ beta_g,
                     const float* __restrict__ mean_g,  const float* __restrict__ var_g,
                     float* __restrict__ out)
{
    __shared__ __align__(16) __half wl_s[128 * WPITCH];
    __shared__ __align__(16) __half wg_s[128 * WPITCH];
    __shared__ __align__(16) __half f_s[KT * FPITCH];
    __shared__ float sBN[4][128];

    const int tid  = threadIdx.x;
    const int wid  = tid >> 5;
    const int lane = tid & 31;

    const int col0 = blockIdx.x * 128;
    const int row0 = blockIdx.y * 128;
    const int b    = blockIdx.z;

    if (tid < 128) {
        int r = row0 + tid;
        float sl = gamma_l[r] / sqrtf(var_l[r] + 1e-5f);
        sBN[0][tid] = sl;
        sBN[1][tid] = beta_l[r] - mean_l[r] * sl;
        float sg = gamma_g[r] / sqrtf(var_g[r] + 1e-5f);
        sBN[2][tid] = sg;
        sBN[3][tid] = beta_g[r] - mean_g[r] * sg;
    }

    const float* fb = feat + (size_t)b * CDIM * NPTS;

    const int wm   = tid >> 1;
    const int wk16 = (tid & 1) * 16;
    const int fk   = tid >> 3;
    const int fn16 = (tid & 7) * 16;

    const float* wlp = wl + (size_t)(row0 + wm) * CDIM + wk16;
    const float* wgp = wg + (size_t)(row0 + wm) * CDIM + wk16;
    const float* fp  = fb + (size_t)fk * NPTS + col0 + fn16;

    const uint32_t wl_u = smem_to_u32(wl_s);
    const uint32_t wg_u = smem_to_u32(wg_s);
    const uint32_t f_u  = smem_to_u32(f_s);
    const int wmrow = (wid & 1) * 64;
    const int wncol = (wid >> 1) * 32;

    const uint32_t a_off = (uint32_t)((wmrow + (lane & 15)) * WPITCH + (lane >> 4) * 8) * 2;
    const uint32_t al_addr = wl_u + a_off;
    const uint32_t ag_addr = wg_u + a_off;
    const uint32_t b_addr  = f_u + (uint32_t)((lane & 15) * FPITCH + wncol) * 2;

    float d[2][4][4][4];
#pragma unroll
    for (int m = 0; m < 2; ++m)
#pragma unroll
        for (int i = 0; i < 4; ++i)
#pragma unroll
            for (int j = 0; j < 4; ++j)
#pragma unroll
                for (int q = 0; q < 4; ++q) d[m][i][j][q] = 0.f;

    uint32_t hl[8], hg[8], hf[8];

#define LDG_TILE(K0)                                                           \
    do {                                                                       \
        const float* p = wlp + (K0);                                           \
        float4 v0 = *(const float4*)(p),      v1 = *(const float4*)(p + 4);    \
        float4 v2 = *(const float4*)(p + 8),  v3 = *(const float4*)(p + 12);   \
        hl[0] = f22h(v0.x, v0.y); hl[1] = f22h(v0.z, v0.w);                    \
        hl[2] = f22h(v1.x, v1.y); hl[3] = f22h(v1.z, v1.w);                    \
        hl[4] = f22h(v2.x, v2.y); hl[5] = f22h(v2.z, v2.w);                    \
        hl[6] = f22h(v3.x, v3.y); hl[7] = f22h(v3.z, v3.w);                    \
        p = wgp + (K0);                                                        \
        v0 = *(const float4*)(p);      v1 = *(const float4*)(p + 4);           \
        v2 = *(const float4*)(p + 8);  v3 = *(const float4*)(p + 12);          \
        hg[0] = f22h(v0.x, v0.y); hg[1] = f22h(v0.z, v0.w);                    \
        hg[2] = f22h(v1.x, v1.y); hg[3] = f22h(v1.z, v1.w);                    \
        hg[4] = f22h(v2.x, v2.y); hg[5] = f22h(v2.z, v2.w);                    \
        hg[6] = f22h(v3.x, v3.y); hg[7] = f22h(v3.z, v3.w);                    \
        p = fp + (size_t)(K0) * NPTS;                                          \
        v0 = *(const float4*)(p);      v1 = *(const float4*)(p + 4);           \
        v2 = *(const float4*)(p + 8);  v3 = *(const float4*)(p + 12);          \
        hf[0] = f22h(v0.x, v0.y); hf[1] = f22h(v0.z, v0.w);                    \
        hf[2] = f22h(v1.x, v1.y); hf[3] = f22h(v1.z, v1.w);                    \
        hf[4] = f22h(v2.x, v2.y); hf[5] = f22h(v2.z, v2.w);                    \
        hf[6] = f22h(v3.x, v3.y); hf[7] = f22h(v3.z, v3.w);                    \
    } while (0)

    LDG_TILE(0);

    for (int kc = 0; kc < NKT; ++kc) {
        *(uint4*)&wl_s[wm * WPITCH + wk16]     = make_uint4(hl[0], hl[1], hl[2], hl[3]);
        *(uint4*)&wl_s[wm * WPITCH + wk16 + 8] = make_uint4(hl[4], hl[5], hl[6], hl[7]);
        *(uint4*)&wg_s[wm * WPITCH + wk16]     = make_uint4(hg[0], hg[1], hg[2], hg[3]);
        *(uint4*)&wg_s[wm * WPITCH + wk16 + 8] = make_uint4(hg[4], hg[5], hg[6], hg[7]);
        *(uint4*)&f_s[fk * FPITCH + fn16]      = make_uint4(hf[0], hf[1], hf[2], hf[3]);
        *(uint4*)&f_s[fk * FPITCH + fn16 + 8]  = make_uint4(hf[4], hf[5], hf[6], hf[7]);
        __syncthreads();

        if (kc + 1 < NKT) LDG_TILE((kc + 1) * KT);

#pragma unroll
        for (int ks = 0; ks < 2; ++ks) {
            uint32_t b0[4], b1[4];
#pragma unroll
            for (int nf = 0; nf < 4; ++nf)
                ldsm_x2t(b0[nf], b1[nf],
                         b_addr + (uint32_t)(ks * 16 * FPITCH + nf * 8) * 2);
#pragma unroll
            for (int mf = 0; mf < 4; ++mf) {
                uint32_t a0, a1, a2, a3;
                ldsm_x4(a0, a1, a2, a3,
                        al_addr + (uint32_t)(mf * 16 * WPITCH) * 2 + ks * 32);
#pragma unroll
                for (int nf = 0; nf < 4; ++nf)
                    mma_f16(d[0][mf][nf], a0, a1, a2, a3, b0[nf], b1[nf]);
                ldsm_x4(a0, a1, a2, a3,
                        ag_addr + (uint32_t)(mf * 16 * WPITCH) * 2 + ks * 32);
#pragma unroll
                for (int nf = 0; nf < 4; ++nf)
                    mma_f16(d[1][mf][nf], a0, a1, a2, a3, b0[nf], b1[nf]);
            }
        }
        __syncthreads();
    }

    const int g = lane >> 2;
    const int t = lane & 3;
#pragma unroll
    for (int mf = 0; mf < 4; ++mf) {
#pragma unroll
        for (int rr = 0; rr < 2; ++rr) {
            int rloc = wmrow + mf * 16 + g + rr * 8;
            float sl = sBN[0][rloc], ol = sBN[1][rloc];
            float sg = sBN[2][rloc], og = sBN[3][rloc];
            float* orow = out + ((size_t)b * CDIM + row0 + rloc) * NPTS
                              + col0 + wncol + t * 2;
#pragma unroll
            for (int nf = 0; nf < 4; ++nf) {
                float2 v;
                v.x = fmaxf(d[0][mf][nf][rr * 2 + 0] * sl + ol, 0.f)
                    + fmaxf(d[1][mf][nf][rr * 2 + 0] * sg + og, 0.f);
                v.y = fmaxf(d[0][mf][nf][rr * 2 + 1] * sl + ol, 0.f)
                    + fmaxf(d[1][mf][nf][rr * 2 + 1] * sg + og, 0.f);
                *(float2*)(orow + nf * 8) = v;
            }
        }
    }
}

// ---------------------------------------------------------------------------
// Launch: out = [ enhanced (B,C,N) f32 | idx (B,N,K) as f32 ]
// KNN branch runs on a forked stream concurrently with the GEMM.
// ---------------------------------------------------------------------------
extern "C" void kernel_launch(void* const* d_in, const int* in_sizes, int n_in,
                              void* d_out, int out_size)
{
    const float* xyz     = (const float*)d_in[0];
    const float* feat    = (const float*)d_in[1];
    const float* wl      = (const float*)d_in[2];
    const float* gamma_l = (const float*)d_in[3];
    const float* beta_l  = (const float*)d_in[4];
    const float* mean_l  = (const float*)d_in[5];
    const float* var_l   = (const float*)d_in[6];
    const float* wg      = (const float*)d_in[7];
    const float* gamma_g = (const float*)d_in[8];
    const float* beta_g  = (const float*)d_in[9];
    const float* mean_g  = (const float*)d_in[10];
    const float* var_g   = (const float*)d_in[11];

    float* out     = (float*)d_out;
    float* out_idx = out + (size_t)BATCH * CDIM * NPTS;

    // Fork a side stream for the KNN branch (handles deliberately not
    // destroyed: destroying capture-involved handles mid-capture is unsafe;
    // kernel_launch runs only a handful of times, no device memory involved).
    cudaStream_t s2;
    cudaEvent_t e_fork, e_join;
    cudaStreamCreateWithFlags(&s2, cudaStreamNonBlocking);
    cudaEventCreateWithFlags(&e_fork, cudaEventDisableTiming);
    cudaEventCreateWithFlags(&e_join, cudaEventDisableTiming);

    cudaEventRecord(e_fork, 0);
    cudaStreamWaitEvent(s2, e_fork, 0);

    // --- KNN branch on s2 ---
    dim3 gk(NPTS / 256, NCHUNK, BATCH);
    knn_partial_kernel<<<gk, 256, 0, s2>>>(xyz);
    knn_merge_kernel<<<(BATCH * NPTS) / 256, 256, 0, s2>>>(out_idx);
    cudaEventRecord(e_join, s2);

    // --- GEMM branch on the main stream (concurrent) ---
    dim3 gg(NPTS / 128, CDIM / 128, BATCH);
    gemm_mma_kernel<<<gg, 256>>>(feat, wl, wg,
                                 gamma_l, beta_l, mean_l, var_l,
                                 gamma_g, beta_g, mean_g, var_g,
                                 out);

    cudaStreamWaitEvent(0, e_join, 0);
}

// round 14
// speedup vs baseline: 1.0015x; 1.0015x over previous
#include <cuda_runtime.h>
#include <cuda_fp16.h>
#include <math.h>
#include <stdint.h>

// Problem shape (fixed by setup_inputs)
#define BATCH 4
#define CDIM  512
#define NPTS  8192
#define KNN   16
#define NCHUNK 4
#define KNN_CH (NPTS / NCHUNK)   // 2048 candidates per chunk CTA

// ===========================================================================
// helpers
// ===========================================================================
__device__ __forceinline__ uint32_t smem_to_u32(const void* p) {
    uint32_t a;
    asm("{ .reg .u64 t; cvta.to.shared.u64 t, %1; cvt.u32.u64 %0, t; }" : "=r"(a) : "l"(p));
    return a;
}
__device__ __forceinline__ uint32_t f22h(float a, float b) {
    __half2 h = __floats2half2_rn(a, b);
    return *reinterpret_cast<uint32_t*>(&h);
}
__device__ __forceinline__ void ldsm_x4(uint32_t& r0, uint32_t& r1, uint32_t& r2,
                                        uint32_t& r3, uint32_t addr) {
    asm volatile("ldmatrix.sync.aligned.m8n8.x4.shared.b16 {%0,%1,%2,%3}, [%4];"
                 : "=r"(r0), "=r"(r1), "=r"(r2), "=r"(r3) : "r"(addr));
}
__device__ __forceinline__ void ldsm_x2t(uint32_t& r0, uint32_t& r1, uint32_t addr) {
    asm volatile("ldmatrix.sync.aligned.m8n8.x2.trans.shared.b16 {%0,%1}, [%2];"
                 : "=r"(r0), "=r"(r1) : "r"(addr));
}
__device__ __forceinline__ void mma_f16(float* d, uint32_t a0, uint32_t a1,
                                        uint32_t a2, uint32_t a3,
                                        uint32_t b0, uint32_t b1) {
    asm volatile(
        "mma.sync.aligned.m16n8k16.row.col.f32.f16.f16.f32 "
        "{%0,%1,%2,%3}, {%4,%5,%6,%7}, {%8,%9}, {%0,%1,%2,%3};"
        : "+f"(d[0]), "+f"(d[1]), "+f"(d[2]), "+f"(d[3])
        : "r"(a0), "r"(a1), "r"(a2), "r"(a3), "r"(b0), "r"(b1));
}

// Partial top-16 scratch: [b][n][chunk][16]
__device__ float pd_buf[(size_t)BATCH * NPTS * NCHUNK * KNN];
__device__ int   pi_buf[(size_t)BATCH * NPTS * NCHUNK * KNN];

// ===========================================================================
// KNN partial kernel: grid (queryBlock=32, chunk=4, batch=4) = 512 CTAs.
// Each CTA scans ONE 2048-candidate chunk for its 256 queries and emits a
// sorted (desc) partial top-16 per query.
// Arithmetic replicates the reference's fp32 roundings exactly:
//   xx  = ((x*x) + (y*y)) + (z*z)
//   dot = fma(z,z', fma(y,y', x*x'))
//   d   = fma(2, dot, -xx_n) - xx_m
// Scan m ascending + strict '>' => lower index first on ties (lax.top_k).
// ===========================================================================
__global__ __launch_bounds__(256, 3)
void knn_partial_kernel(const float* __restrict__ xyz)
{
    __shared__ float4 sh[KNN_CH];
    const int b     = blockIdx.z;
    const int chunk = blockIdx.y;
    const float* xb = xyz + (size_t)b * 3 * NPTS;

    const int base = chunk * KNN_CH;
    for (int m = threadIdx.x; m < KNN_CH; m += blockDim.x) {
        float x = xb[base + m];
        float y = xb[NPTS + base + m];
        float z = xb[2 * NPTS + base + m];
        float xx = __fadd_rn(__fadd_rn(__fmul_rn(x, x), __fmul_rn(y, y)),
                             __fmul_rn(z, z));
        sh[m] = make_float4(x, y, z, xx);
    }

    const int n = blockIdx.x * blockDim.x + threadIdx.x;
    float qx = xb[n], qy = xb[NPTS + n], qz = xb[2 * NPTS + n];
    const float nqxx = -__fadd_rn(__fadd_rn(__fmul_rn(qx, qx), __fmul_rn(qy, qy)),
                                  __fmul_rn(qz, qz));

    float dk[KNN];
    int   ik[KNN];
#pragma unroll
    for (int j = 0; j < KNN; ++j) { dk[j] = -3.402823466e38f; ik[j] = 0; }

    __syncthreads();

#pragma unroll 4
    for (int mm = 0; mm < KNN_CH; ++mm) {
        float4 cd = sh[mm];
        float dot = __fmaf_rn(qz, cd.z, __fmaf_rn(qy, cd.y, __fmul_rn(qx, cd.x)));
        float d = __fsub_rn(__fmaf_rn(2.0f, dot, nqxx), cd.w);
        if (d > dk[KNN - 1]) {
            dk[KNN - 1] = d;
            ik[KNN - 1] = base + mm;
#pragma unroll
            for (int j = KNN - 1; j > 0; --j) {
                if (dk[j] > dk[j - 1]) {
                    float td = dk[j]; dk[j] = dk[j - 1]; dk[j - 1] = td;
                    int   ti = ik[j]; ik[j] = ik[j - 1]; ik[j - 1] = ti;
                }
            }
        }
    }

    const size_t o = (((size_t)b * NPTS + n) * NCHUNK + chunk) * KNN;
#pragma unroll
    for (int j = 0; j < KNN; ++j) { pd_buf[o + j] = dk[j]; pi_buf[o + j] = ik[j]; }
}

// ===========================================================================
// Merge kernel: 4-way merge of sorted partial lists per query.
// Strict '>' with chunk index ascending => on ties the lower chunk (= lower
// global index) wins; within-chunk order already index-ascending on ties.
// Exactly reproduces the single-scan global top-16 ordering.
// ===========================================================================
__global__ __launch_bounds__(256)
void knn_merge_kernel(float* __restrict__ out_idx)
{
    const int g = blockIdx.x * blockDim.x + threadIdx.x;   // b*NPTS + n
    const float* pd = pd_buf + (size_t)g * NCHUNK * KNN;
    const int*   pi = pi_buf + (size_t)g * NCHUNK * KNN;
    float* o = out_idx + (size_t)g * KNN;

    int p[NCHUNK] = {0, 0, 0, 0};
#pragma unroll
    for (int j = 0; j < KNN; ++j) {
        float best = -3.402823466e38f;
        int bc = 0;
#pragma unroll
        for (int c = 0; c < NCHUNK; ++c) {
            if (p[c] < KNN) {
                float v = pd[c * KNN + p[c]];
                if (v > best) { best = v; bc = c; }
            }
        }
        o[j] = (float)pi[bc * KNN + p[bc]];
        p[bc]++;
    }
}

// ===========================================================================
// Dual fp16 mma.sync GEMM + BN + ReLU + add. (unchanged from R10 pass)
// ===========================================================================
#define KT 32
#define WPITCH 40
#define FPITCH 136
#define NKT (CDIM / KT)

__global__ __launch_bounds__(256, 1)
void gemm_mma_kernel(const float* __restrict__ feat,
                     const float* __restrict__ wl,
                     const float* __restrict__ wg,
                     const float* __restrict__ gamma_l, const float* __restrict__ beta_l,
                     const float* __restrict__ mean_l,  const float* __restrict__ var_l,
                     const float* __restrict__ gamma_g, const float* __restrict__ beta_g,
                     const float* __restrict__ mean_g,  const float* __restrict__ var_g,
                     float* __restrict__ out)
{
    __shared__ __align__(16) __half wl_s[128 * WPITCH];
    __shared__ __align__(16) __half wg_s[128 * WPITCH];
    __shared__ __align__(16) __half f_s[KT * FPITCH];
    __shared__ float sBN[4][128];

    const int tid  = threadIdx.x;
    const int wid  = tid >> 5;
    const int lane = tid & 31;

    const int col0 = blockIdx.x * 128;
    const int row0 = blockIdx.y * 128;
    const int b    = blockIdx.z;

    if (tid < 128) {
        int r = row0 + tid;
        float sl = gamma_l[r] / sqrtf(var_l[r] + 1e-5f);
        sBN[0][tid] = sl;
        sBN[1][tid] = beta_l[r] - mean_l[r] * sl;
        float sg = gamma_g[r] / sqrtf(var_g[r] + 1e-5f);
        sBN[2][tid] = sg;
        sBN[3][tid] = beta_g[r] - mean_g[r] * sg;
    }

    const float* fb = feat + (size_t)b * CDIM * NPTS;

    const int wm   = tid >> 1;
    const int wk16 = (tid & 1) * 16;
    const int fk   = tid >> 3;
    const int fn16 = (tid & 7) * 16;

    const float* wlp = wl + (size_t)(row0 + wm) * CDIM + wk16;
    const float* wgp = wg + (size_t)(row0 + wm) * CDIM + wk16;
    const float* fp  = fb + (size_t)fk * NPTS + col0 + fn16;

    const uint32_t wl_u = smem_to_u32(wl_s);
    const uint32_t wg_u = smem_to_u32(wg_s);
    const uint32_t f_u  = smem_to_u32(f_s);
    const int wmrow = (wid & 1) * 64;
    const int wncol = (wid >> 1) * 32;

    const uint32_t a_off = (uint32_t)((wmrow + (lane & 15)) * WPITCH + (lane >> 4) * 8) * 2;
    const uint32_t al_addr = wl_u + a_off;
    const uint32_t ag_addr = wg_u + a_off;
    const uint32_t b_addr  = f_u + (uint32_t)((lane & 15) * FPITCH + wncol) * 2;

    float d[2][4][4][4];
#pragma unroll
    for (int m = 0; m < 2; ++m)
#pragma unroll
        for (int i = 0; i < 4; ++i)
#pragma unroll
            for (int j = 0; j < 4; ++j)
#pragma unroll
                for (int q = 0; q < 4; ++q) d[m][i][j][q] = 0.f;

    uint32_t hl[8], hg[8], hf[8];

#define LDG_TILE(K0)                                                           \
    do {                                                                       \
        const float* p = wlp + (K0);                                           \
        float4 v0 = *(const float4*)(p),      v1 = *(const float4*)(p + 4);    \
        float4 v2 = *(const float4*)(p + 8),  v3 = *(const float4*)(p + 12);   \
        hl[0] = f22h(v0.x, v0.y); hl[1] = f22h(v0.z, v0.w);                    \
        hl[2] = f22h(v1.x, v1.y); hl[3] = f22h(v1.z, v1.w);                    \
        hl[4] = f22h(v2.x, v2.y); hl[5] = f22h(v2.z, v2.w);                    \
        hl[6] = f22h(v3.x, v3.y); hl[7] = f22h(v3.z, v3.w);                    \
        p = wgp + (K0);                                                        \
        v0 = *(const float4*)(p);      v1 = *(const float4*)(p + 4);           \
        v2 = *(const float4*)(p + 8);  v3 = *(const float4*)(p + 12);          \
        hg[0] = f22h(v0.x, v0.y); hg[1] = f22h(v0.z, v0.w);                    \
        hg[2] = f22h(v1.x, v1.y); hg[3] = f22h(v1.z, v1.w);                    \
        hg[4] = f22h(v2.x, v2.y); hg[5] = f22h(v2.z, v2.w);                    \
        hg[6] = f22h(v3.x, v3.y); hg[7] = f22h(v3.z, v3.w);                    \
        p = fp + (size_t)(K0) * NPTS;                                          \
        v0 = *(const float4*)(p);      v1 = *(const float4*)(p + 4);           \
        v2 = *(const float4*)(p + 8);  v3 = *(const float4*)(p + 12);          \
        hf[0] = f22h(v0.x, v0.y); hf[1] = f22h(v0.z, v0.w);                    \
        hf[2] = f22h(v1.x, v1.y); hf[3] = f22h(v1.z, v1.w);                    \
        hf[4] = f22h(v2.x, v2.y); hf[5] = f22h(v2.z, v2.w);                    \
        hf[6] = f22h(v3.x, v3.y); hf[7] = f22h(v3.z, v3.w);                    \
    } while (0)

    LDG_TILE(0);

    for (int kc = 0; kc < NKT; ++kc) {
        *(uint4*)&wl_s[wm * WPITCH + wk16]     = make_uint4(hl[0], hl[1], hl[2], hl[3]);
        *(uint4*)&wl_s[wm * WPITCH + wk16 + 8] = make_uint4(hl[4], hl[5], hl[6], hl[7]);
        *(uint4*)&wg_s[wm * WPITCH + wk16]     = make_uint4(hg[0], hg[1], hg[2], hg[3]);
        *(uint4*)&wg_s[wm * WPITCH + wk16 + 8] = make_uint4(hg[4], hg[5], hg[6], hg[7]);
        *(uint4*)&f_s[fk * FPITCH + fn16]      = make_uint4(hf[0], hf[1], hf[2], hf[3]);
        *(uint4*)&f_s[fk * FPITCH + fn16 + 8]  = make_uint4(hf[4], hf[5], hf[6], hf[7]);
        __syncthreads();

        if (kc + 1 < NKT) LDG_TILE((kc + 1) * KT);

#pragma unroll
        for (int ks = 0; ks < 2; ++ks) {
            uint32_t b0[4], b1[4];
#pragma unroll
            for (int nf = 0; nf < 4; ++nf)
                ldsm_x2t(b0[nf], b1[nf],
                         b_addr + (uint32_t)(ks * 16 * FPITCH + nf * 8) * 2);
#pragma unroll
            for (int mf = 0; mf < 4; ++mf) {
                uint32_t a0, a1, a2, a3;
                ldsm_x4(a0, a1, a2, a3,
                        al_addr + (uint32_t)(mf * 16 * WPITCH) * 2 + ks * 32);
#pragma unroll
                for (int nf = 0; nf < 4; ++nf)
                    mma_f16(d[0][mf][nf], a0, a1, a2, a3, b0[nf], b1[nf]);
                ldsm_x4(a0, a1, a2, a3,
                        ag_addr + (uint32_t)(mf * 16 * WPITCH) * 2 + ks * 32);
#pragma unroll
                for (int nf = 0; nf < 4; ++nf)
                    mma_f16(d[1][mf][nf], a0, a1, a2, a3, b0[nf], b1[nf]);
            }
        }
        __syncthreads();
    }

    const int g = lane >> 2;
    const int t = lane & 3;
#pragma unroll
    for (int mf = 0; mf < 4; ++mf) {
#pragma unroll
        for (int rr = 0; rr < 2; ++rr) {
            int rloc = wmrow + mf * 16 + g + rr * 8;
            float sl = sBN[0][rloc], ol = sBN[1][rloc];
            float sg = sBN[2][rloc], og = sBN[3][rloc];
            float* orow = out + ((size_t)b * CDIM + row0 + rloc) * NPTS
                              + col0 + wncol + t * 2;
#pragma unroll
            for (int nf = 0; nf < 4; ++nf) {
                float2 v;
                v.x = fmaxf(d[0][mf][nf][rr * 2 + 0] * sl + ol, 0.f)
                    + fmaxf(d[1][mf][nf][rr * 2 + 0] * sg + og, 0.f);
                v.y = fmaxf(d[0][mf][nf][rr * 2 + 1] * sl + ol, 0.f)
                    + fmaxf(d[1][mf][nf][rr * 2 + 1] * sg + og, 0.f);
                *(float2*)(orow + nf * 8) = v;
            }
        }
    }
}

// ---------------------------------------------------------------------------
// Launch: out = [ enhanced (B,C,N) f32 | idx (B,N,K) as f32 ]
// KNN branch runs on a forked stream concurrently with the GEMM.
// ---------------------------------------------------------------------------
extern "C" void kernel_launch(void* const* d_in, const int* in_sizes, int n_in,
                              void* d_out, int out_size)
{
    const float* xyz     = (const float*)d_in[0];
    const float* feat    = (const float*)d_in[1];
    const float* wl      = (const float*)d_in[2];
    const float* gamma_l = (const float*)d_in[3];
    const float* beta_l  = (const float*)d_in[4];
    const float* mean_l  = (const float*)d_in[5];
    const float* var_l   = (const float*)d_in[6];
    const float* wg      = (const float*)d_in[7];
    const float* gamma_g = (const float*)d_in[8];
    const float* beta_g  = (const float*)d_in[9];
    const float* mean_g  = (const float*)d_in[10];
    const float* var_g   = (const float*)d_in[11];

    float* out     = (float*)d_out;
    float* out_idx = out + (size_t)BATCH * CDIM * NPTS;

    // Fork a side stream for the KNN branch (handles deliberately not
    // destroyed: destroying capture-involved handles mid-capture is unsafe;
    // kernel_launch runs only a handful of times, no device memory involved).
    cudaStream_t s2;
    cudaEvent_t e_fork, e_join;
    cudaStreamCreateWithFlags(&s2, cudaStreamNonBlocking);
    cudaEventCreateWithFlags(&e_fork, cudaEventDisableTiming);
    cudaEventCreateWithFlags(&e_join, cudaEventDisableTiming);

    cudaEventRecord(e_fork, 0);
    cudaStreamWaitEvent(s2, e_fork, 0);

    // --- KNN branch on s2 ---
    dim3 gk(NPTS / 256, NCHUNK, BATCH);
    knn_partial_kernel<<<gk, 256, 0, s2>>>(xyz);
    knn_merge_kernel<<<(BATCH * NPTS) / 256, 256, 0, s2>>>(out_idx);
    cudaEventRecord(e_join, s2);

    // --- GEMM branch on the main stream (concurrent) ---
    dim3 gg(NPTS / 128, CDIM / 128, BATCH);
    gemm_mma_kernel<<<gg, 256>>>(feat, wl, wg,
                                 gamma_l, beta_l, mean_l, var_l,
                                 gamma_g, beta_g, mean_g, var_g,
                                 out);

    cudaStreamWaitEvent(0, e_join, 0);
}